// round 9
// baseline (speedup 1.0000x reference)
#include <cuda_runtime.h>
#include <math.h>

#define BB      32
#define HH      32
#define KVHN    8
#define DD      128
#define SS      2048
#define NCHUNK  37            // 37*32 = 1184 CTAs = 2 exact waves of 592
#define CSM     56            // max positions per chunk (last chunk: 32)
#define HCSM    28            // positions per table pass
#define NT      256           // 8 warps = 8 kv heads
#define SCALE   0.08838834764831845f
#define ROWF    (KVHN*DD)     // floats per slot row (1024)
#define FULLM   0xffffffffu

__device__ float g_acc[(size_t)BB * NCHUNK * HH * DD];  // ~19.4 MB
__device__ float g_m[BB * NCHUNK * HH];
__device__ float g_l[BB * NCHUNK * HH];

__device__ __forceinline__ void l2_prefetch(const void* p) {
    asm volatile("prefetch.global.L2 [%0];" :: "l"(p));
}

// fp32 Cody-Waite reduction into [-pi,pi], then MUFU fast sin/cos.
__device__ __forceinline__ void rope_sincos(float ang, float* s, float* c) {
    const float INV2PI = 0.15915494309189535f;
    const float C1 = 6.28125f;
    const float C2 = 0.0019353071795864769f;
    float n = rintf(ang * INV2PI);
    float r = fmaf(-n, C1, ang);
    r = fmaf(-n, C2, r);
    *s = __sinf(r);
    *c = __cosf(r);
}

__global__ __launch_bounds__(NT, 4) void attn_partial(
    const float* __restrict__ q,
    const float* __restrict__ kc,
    const float* __restrict__ vc,
    const int*   __restrict__ slot_map,
    const int*   __restrict__ pos)
{
    __shared__ float  cos_tab[HCSM * 64];         // 7 KB per pass
    __shared__ float  sin_tab[HCSM * 64];         // 7 KB
    __shared__ float4 q_sm[KVHN * 4 * 2 * 16];    // 16 KB  [head j][lo/hi][c]
    __shared__ float4 sc_sm[KVHN * CSM];          // 7 KB   scores -> exp weights
    __shared__ int    slot_sm[CSM];
    __shared__ float  pos_sm[CSM];
    __shared__ float  invf_sm[64];

    const int b     = blockIdx.y;
    const int chunk = blockIdx.x;
    const int s0    = chunk * CSM;
    const int nrows = (SS - s0 < CSM) ? (SS - s0) : CSM;   // 56 or 32
    const int tid   = threadIdx.x;
    const int w     = tid >> 5;            // warp = kv head
    const int l     = tid & 31;
    const int c     = l & 15;              // float4 chunk within row (K phase)
    const int r     = l >> 4;              // row parity within pair

    if (tid < 64) {
        float fi = (float)tid * 0.015625f;
        invf_sm[tid] = expf(-fi * 9.210340371976184f);
    }
    if (tid < CSM) {
        if (tid < nrows) {
            slot_sm[tid] = slot_map[b * SS + s0 + tid];
            pos_sm[tid]  = (float)pos[b * SS + s0 + tid];
        } else {
            slot_sm[tid] = -1;
            pos_sm[tid]  = 0.f;
        }
    }
    __syncthreads();

    // Warm L2 for the first 32 K rows while the prologue runs.
    {
        int sw = tid >> 3;
        int lc = tid & 7;
        int slot = slot_sm[sw];
        if (slot >= 0)
            l2_prefetch(kc + (size_t)slot * ROWF + (w & 3) * 2 * DD + lc * 32);
    }

    // Rope q (4 heads per warp) for dims {4c..4c+3, +64}; fold SCALE; store to shared.
    if (r == 0) {
        float pq = (float)pos[b * SS + SS - 1];
        float cq[4], sq[4];
        #pragma unroll
        for (int i = 0; i < 4; i++)
            rope_sincos(pq * invf_sm[4 * c + i], &sq[i], &cq[i]);
        #pragma unroll
        for (int j = 0; j < 4; j++) {
            const float4* qp = (const float4*)(q + ((size_t)(b * HH + w * 4 + j)) * DD);
            float4 alo = qp[c];
            float4 ahi = qp[c + 16];
            float4 ql, qh;
            ql.x = SCALE * (alo.x * cq[0] - ahi.x * sq[0]);
            qh.x = SCALE * (ahi.x * cq[0] + alo.x * sq[0]);
            ql.y = SCALE * (alo.y * cq[1] - ahi.y * sq[1]);
            qh.y = SCALE * (ahi.y * cq[1] + alo.y * sq[1]);
            ql.z = SCALE * (alo.z * cq[2] - ahi.z * sq[2]);
            qh.z = SCALE * (ahi.z * cq[2] + alo.z * sq[2]);
            ql.w = SCALE * (alo.w * cq[3] - ahi.w * sq[3]);
            qh.w = SCALE * (ahi.w * cq[3] + alo.w * sq[3]);
            q_sm[((w * 4 + j) * 2 + 0) * 16 + c] = ql;
            q_sm[((w * 4 + j) * 2 + 1) * 16 + c] = qh;
        }
    }

    // ---- K phase in two passes of up to HCSM positions ----
    float m0 = -1e30f, m1 = -1e30f, m2 = -1e30f, m3 = -1e30f;

    #pragma unroll
    for (int pass = 0; pass < 2; pass++) {
        const int base      = pass * HCSM;
        const int rows_pass = (nrows - base < HCSM) ? (nrows - base) : HCSM;  // 28, 28 or 4

        // build cos/sin for positions [base, base+rows_pass) (padded rows harmless)
        for (int idx = tid; idx < HCSM * 64; idx += NT) {
            int s = idx >> 6;
            int i = idx & 63;
            float sv, cv;
            rope_sincos(pos_sm[base + s] * invf_sm[i], &sv, &cv);
            cos_tab[idx] = cv;
            sin_tab[idx] = sv;
        }
        __syncthreads();

        #pragma unroll 4
        for (int sp = 0; sp < rows_pass; sp += 2) {
            const int sl = sp + r;                 // table-local position
            const int s  = base + sl;              // chunk-local position
            const int slot = slot_sm[s];

            // prefetch K row 12 positions ahead into L2
            {
                int sf = s + 12;
                if (sf < nrows) {
                    int slotf = slot_sm[sf];
                    if (slotf >= 0) {
                        const float* pp = kc + (size_t)slotf * ROWF + w * DD + 4 * c;
                        l2_prefetch(pp);
                        l2_prefetch(pp + 64);
                    }
                }
            }

            float4 klo = make_float4(0.f, 0.f, 0.f, 0.f);
            float4 khi = make_float4(0.f, 0.f, 0.f, 0.f);
            if (slot >= 0) {
                const float* kp = kc + (size_t)slot * ROWF + w * DD + 4 * c;
                klo = *(const float4*)kp;
                khi = *(const float4*)(kp + 64);
            }
            const float4 co = *(const float4*)&cos_tab[sl * 64 + 4 * c];
            const float4 si = *(const float4*)&sin_tab[sl * 64 + 4 * c];

            float rlx = klo.x * co.x - khi.x * si.x, rhx = khi.x * co.x + klo.x * si.x;
            float rly = klo.y * co.y - khi.y * si.y, rhy = khi.y * co.y + klo.y * si.y;
            float rlz = klo.z * co.z - khi.z * si.z, rhz = khi.z * co.z + klo.z * si.z;
            float rlw = klo.w * co.w - khi.w * si.w, rhw = khi.w * co.w + klo.w * si.w;

            float p[4];
            #pragma unroll
            for (int j = 0; j < 4; j++) {
                float4 ql = q_sm[((w * 4 + j) * 2 + 0) * 16 + c];
                float4 qh = q_sm[((w * 4 + j) * 2 + 1) * 16 + c];
                p[j] = ql.x * rlx + ql.y * rly + ql.z * rlz + ql.w * rlw
                     + qh.x * rhx + qh.y * rhy + qh.z * rhz + qh.w * rhw;
            }
            #pragma unroll
            for (int off = 1; off <= 8; off <<= 1) {
                p[0] += __shfl_xor_sync(FULLM, p[0], off);
                p[1] += __shfl_xor_sync(FULLM, p[1], off);
                p[2] += __shfl_xor_sync(FULLM, p[2], off);
                p[3] += __shfl_xor_sync(FULLM, p[3], off);
            }
            m0 = fmaxf(m0, p[0]); m1 = fmaxf(m1, p[1]);
            m2 = fmaxf(m2, p[2]); m3 = fmaxf(m3, p[3]);
            if (c == 0) sc_sm[w * CSM + s] = make_float4(p[0], p[1], p[2], p[3]);
        }
        __syncthreads();   // protect table before rebuild / reuse
    }

    // merge the two half-warp maxima
    m0 = fmaxf(m0, __shfl_xor_sync(FULLM, m0, 16));
    m1 = fmaxf(m1, __shfl_xor_sync(FULLM, m1, 16));
    m2 = fmaxf(m2, __shfl_xor_sync(FULLM, m2, 16));
    m3 = fmaxf(m3, __shfl_xor_sync(FULLM, m3, 16));

    // lead-in prefetch of the first 8 V rows
    if (l < 4) {
        #pragma unroll
        for (int s = 0; s < 8; s++) {
            int slot = slot_sm[s];
            if (slot >= 0)
                l2_prefetch(vc + (size_t)slot * ROWF + w * DD + l * 32);
        }
    }

    // ---- scores -> exp weights in shared; accumulate l-sums ----
    float l0 = 0.f, l1 = 0.f, l2 = 0.f, l3 = 0.f;
    for (int s = l; s < nrows; s += 32) {
        float4 sc = sc_sm[w * CSM + s];
        sc.x = __expf(sc.x - m0); sc.y = __expf(sc.y - m1);
        sc.z = __expf(sc.z - m2); sc.w = __expf(sc.w - m3);
        sc_sm[w * CSM + s] = sc;
        l0 += sc.x; l1 += sc.y; l2 += sc.z; l3 += sc.w;
    }
    #pragma unroll
    for (int off = 16; off > 0; off >>= 1) {
        l0 += __shfl_xor_sync(FULLM, l0, off);
        l1 += __shfl_xor_sync(FULLM, l1, off);
        l2 += __shfl_xor_sync(FULLM, l2, off);
        l3 += __shfl_xor_sync(FULLM, l3, off);
    }
    __syncwarp();

    // ---- V phase: lane owns dims 4l..4l+3, one row per iteration ----
    float4 a0 = make_float4(0,0,0,0), a1 = a0, a2 = a0, a3 = a0;
    #pragma unroll 4
    for (int s = 0; s < nrows; s++) {
        // prefetch V row 8 ahead
        {
            int sf = s + 8;
            if (sf < nrows) {
                int slotf = slot_sm[sf];
                if (slotf >= 0)
                    l2_prefetch(vc + (size_t)slotf * ROWF + w * DD + 4 * l);
            }
        }
        const float4 e = sc_sm[w * CSM + s];     // broadcast
        const int slot = slot_sm[s];
        float4 v4 = make_float4(0.f, 0.f, 0.f, 0.f);
        if (slot >= 0)
            v4 = *(const float4*)(vc + (size_t)slot * ROWF + w * DD + 4 * l);
        a0.x += e.x * v4.x; a0.y += e.x * v4.y; a0.z += e.x * v4.z; a0.w += e.x * v4.w;
        a1.x += e.y * v4.x; a1.y += e.y * v4.y; a1.z += e.y * v4.z; a1.w += e.y * v4.w;
        a2.x += e.z * v4.x; a2.y += e.z * v4.y; a2.z += e.z * v4.z; a2.w += e.z * v4.w;
        a3.x += e.w * v4.x; a3.y += e.w * v4.y; a3.z += e.w * v4.z; a3.w += e.w * v4.w;
    }

    // ---- Write partials (float4, coalesced) ----
    {
        size_t base = (((size_t)b * NCHUNK + chunk) * HH + w * 4) * DD;
        float4* ga = (float4*)g_acc;
        ga[(base >> 2) + l]            = a0;
        ga[((base + DD) >> 2) + l]     = a1;
        ga[((base + 2 * DD) >> 2) + l] = a2;
        ga[((base + 3 * DD) >> 2) + l] = a3;
    }
    if (l == 0) {
        int mb = (b * NCHUNK + chunk) * HH + w * 4;
        g_m[mb + 0] = m0; g_m[mb + 1] = m1; g_m[mb + 2] = m2; g_m[mb + 3] = m3;
        g_l[mb + 0] = l0; g_l[mb + 1] = l1; g_l[mb + 2] = l2; g_l[mb + 3] = l3;
    }
}

// Combine: one block per (b,h); 4 warps x <=10 chunks each; merge via shared.
#define CPW 10   // chunks per warp (4*10 >= 37)
__global__ __launch_bounds__(128) void attn_combine(float* __restrict__ out)
{
    __shared__ float4 osm[4][32];
    __shared__ float  Lsm[4];

    const int bh = blockIdx.x;
    const int b  = bh >> 5;
    const int h  = bh & 31;
    const int wj = threadIdx.x >> 5;
    const int l  = threadIdx.x & 31;

    // global max over 37 chunks: lanes cover chunk l and chunk 32+l
    float ma = g_m[(b * NCHUNK + l) * HH + h];            // chunks 0..31
    float mb2 = (l < NCHUNK - 32) ? g_m[(b * NCHUNK + 32 + l) * HH + h] : -1e30f;
    float M = fmaxf(ma, mb2);
    #pragma unroll
    for (int off = 16; off > 0; off >>= 1)
        M = fmaxf(M, __shfl_xor_sync(FULLM, M, off));

    // precompute alpha factors for this warp's chunks
    float al[CPW];
    #pragma unroll
    for (int k = 0; k < CPW; k++) {
        int cn = wj * CPW + k;
        al[k] = (cn < NCHUNK) ? __expf(g_m[(b * NCHUNK + cn) * HH + h] - M) : 0.f;
    }

    float L = 0.f;
    float4 o = make_float4(0.f, 0.f, 0.f, 0.f);
    #pragma unroll
    for (int k = 0; k < CPW; k++) {
        int cn = wj * CPW + k;
        if (cn < NCHUNK) {
            int idx = (b * NCHUNK + cn) * HH + h;
            L += al[k] * g_l[idx];
            float4 a = ((const float4*)g_acc)[(((size_t)idx * DD) >> 2) + l];
            o.x += al[k] * a.x; o.y += al[k] * a.y;
            o.z += al[k] * a.z; o.w += al[k] * a.w;
        }
    }
    osm[wj][l] = o;
    if (l == 0) Lsm[wj] = L;
    __syncthreads();

    if (wj == 0) {
        float4 t1 = osm[1][l], t2 = osm[2][l], t3 = osm[3][l];
        o.x += t1.x + t2.x + t3.x;
        o.y += t1.y + t2.y + t3.y;
        o.z += t1.z + t2.z + t3.z;
        o.w += t1.w + t2.w + t3.w;
        float inv = 1.0f / (Lsm[0] + Lsm[1] + Lsm[2] + Lsm[3]);
        o.x *= inv; o.y *= inv; o.z *= inv; o.w *= inv;
        ((float4*)out)[(size_t)bh * 32 + l] = o;
    }
}

extern "C" void kernel_launch(void* const* d_in, const int* in_sizes, int n_in,
                              void* d_out, int out_size) {
    const float* query   = (const float*)d_in[0];
    const float* k_cache = (const float*)d_in[1];
    const float* v_cache = (const float*)d_in[2];
    const int*   slots   = (const int*)d_in[3];
    const int*   pos     = (const int*)d_in[4];
    float*       out     = (float*)d_out;

    attn_partial<<<dim3(NCHUNK, BB), NT>>>(query, k_cache, v_cache, slots, pos);
    attn_combine<<<BB * HH, 128>>>(out);
}

// round 10
// speedup vs baseline: 1.4436x; 1.4436x over previous
#include <cuda_runtime.h>
#include <math.h>

#define BB      32
#define HH      32
#define KVHN    8
#define DD      128
#define SS      2048
#define NCHUNK  37            // 36 chunks of 56 rows + 1 chunk of 32; grid 1184 = 2x592
#define CSM     56            // max rows per chunk (buffer size)
#define HPM     28            // max rows per table pass (buffer size)
#define NT      256           // 8 warps = 8 kv heads
#define SCALE   0.08838834764831845f
#define ROWF    (KVHN*DD)     // floats per slot row (1024)
#define FULLM   0xffffffffu

__device__ float g_acc[(size_t)BB * NCHUNK * HH * DD];  // ~19.4 MB
__device__ float g_m[BB * NCHUNK * HH];
__device__ float g_l[BB * NCHUNK * HH];

__device__ __forceinline__ void l2_prefetch(const void* p) {
    asm volatile("prefetch.global.L2 [%0];" :: "l"(p));
}

// fp32 Cody-Waite reduction into [-pi,pi], then MUFU fast sin/cos.
__device__ __forceinline__ void rope_sincos(float ang, float* s, float* c) {
    const float INV2PI = 0.15915494309189535f;
    const float C1 = 6.28125f;
    const float C2 = 0.0019353071795864769f;
    float n = rintf(ang * INV2PI);
    float r = fmaf(-n, C1, ang);
    r = fmaf(-n, C2, r);
    *s = __sinf(r);
    *c = __cosf(r);
}

struct SmemT {
    float  cos_tab[HPM * 64];          // 7 KB
    float  sin_tab[HPM * 64];          // 7 KB
    float4 q_sm[KVHN * 4 * 2 * 16];    // 16 KB
    float4 sc_sm[KVHN * CSM];          // 7 KB
    int    slot_sm[CSM];
    float  pos_sm[CSM];
    float  invf_sm[64];
};

// All loop bounds compile-time: NR rows, two passes of NR/2.
template<int NR>
__device__ __forceinline__ void partial_body(
    SmemT& sm,
    const float* __restrict__ q,
    const float* __restrict__ kc,
    const float* __restrict__ vc,
    int b, int chunk)
{
    constexpr int HP = NR / 2;         // rows per table pass (28 or 16)
    const int tid = threadIdx.x;
    const int w   = tid >> 5;
    const int l   = tid & 31;
    const int c   = l & 15;
    const int r   = l >> 4;

    // Warm L2 for the first 32 K rows while the prologue runs.
    {
        int sw = tid >> 3;
        int lc = tid & 7;
        if (sw < NR) {
            int slot = sm.slot_sm[sw];
            if (slot >= 0)
                l2_prefetch(kc + (size_t)slot * ROWF + (w & 3) * 2 * DD + lc * 32);
        }
    }

    // Rope q (4 heads per warp) for dims {4c..4c+3, +64}; fold SCALE; store to shared.
    if (r == 0) {
        float pq = sm.pos_sm[0] + (float)(SS - 1 - chunk * CSM);  // pos[b][SS-1]; positions are arange
        // NOTE: positions are broadcast arange(S) per reference; pos_sm[0]=s0 so pq=SS-1.
        float cq[4], sq[4];
        #pragma unroll
        for (int i = 0; i < 4; i++)
            rope_sincos(pq * sm.invf_sm[4 * c + i], &sq[i], &cq[i]);
        #pragma unroll
        for (int j = 0; j < 4; j++) {
            const float4* qp = (const float4*)(q + ((size_t)(b * HH + w * 4 + j)) * DD);
            float4 alo = qp[c];
            float4 ahi = qp[c + 16];
            float4 ql, qh;
            ql.x = SCALE * (alo.x * cq[0] - ahi.x * sq[0]);
            qh.x = SCALE * (ahi.x * cq[0] + alo.x * sq[0]);
            ql.y = SCALE * (alo.y * cq[1] - ahi.y * sq[1]);
            qh.y = SCALE * (ahi.y * cq[1] + alo.y * sq[1]);
            ql.z = SCALE * (alo.z * cq[2] - ahi.z * sq[2]);
            qh.z = SCALE * (ahi.z * cq[2] + alo.z * sq[2]);
            ql.w = SCALE * (alo.w * cq[3] - ahi.w * sq[3]);
            qh.w = SCALE * (ahi.w * cq[3] + alo.w * sq[3]);
            sm.q_sm[((w * 4 + j) * 2 + 0) * 16 + c] = ql;
            sm.q_sm[((w * 4 + j) * 2 + 1) * 16 + c] = qh;
        }
    }

    // ---- K phase in two passes of HP positions ----
    float m0 = -1e30f, m1 = -1e30f, m2 = -1e30f, m3 = -1e30f;

    #pragma unroll
    for (int pass = 0; pass < 2; pass++) {
        const int base = pass * HP;
        for (int idx = tid; idx < HP * 64; idx += NT) {
            int s = idx >> 6;
            int i = idx & 63;
            float sv, cv;
            rope_sincos(sm.pos_sm[base + s] * sm.invf_sm[i], &sv, &cv);
            sm.cos_tab[idx] = cv;
            sm.sin_tab[idx] = sv;
        }
        __syncthreads();

        #pragma unroll 4
        for (int sp = 0; sp < HP; sp += 2) {
            const int sl = sp + r;
            const int s  = base + sl;
            const int slot = sm.slot_sm[s];

            // prefetch K row 8 positions ahead into L2
            {
                int sf = s + 8;
                if (sf < NR) {
                    int slotf = sm.slot_sm[sf];
                    if (slotf >= 0) {
                        const float* pp = kc + (size_t)slotf * ROWF + w * DD + 4 * c;
                        l2_prefetch(pp);
                        l2_prefetch(pp + 64);
                    }
                }
            }

            float4 klo = make_float4(0.f, 0.f, 0.f, 0.f);
            float4 khi = make_float4(0.f, 0.f, 0.f, 0.f);
            if (slot >= 0) {
                const float* kp = kc + (size_t)slot * ROWF + w * DD + 4 * c;
                klo = *(const float4*)kp;
                khi = *(const float4*)(kp + 64);
            }
            const float4 co = *(const float4*)&sm.cos_tab[sl * 64 + 4 * c];
            const float4 si = *(const float4*)&sm.sin_tab[sl * 64 + 4 * c];

            float rlx = klo.x * co.x - khi.x * si.x, rhx = khi.x * co.x + klo.x * si.x;
            float rly = klo.y * co.y - khi.y * si.y, rhy = khi.y * co.y + klo.y * si.y;
            float rlz = klo.z * co.z - khi.z * si.z, rhz = khi.z * co.z + klo.z * si.z;
            float rlw = klo.w * co.w - khi.w * si.w, rhw = khi.w * co.w + klo.w * si.w;

            float p[4];
            #pragma unroll
            for (int j = 0; j < 4; j++) {
                float4 ql = sm.q_sm[((w * 4 + j) * 2 + 0) * 16 + c];
                float4 qh = sm.q_sm[((w * 4 + j) * 2 + 1) * 16 + c];
                p[j] = ql.x * rlx + ql.y * rly + ql.z * rlz + ql.w * rlw
                     + qh.x * rhx + qh.y * rhy + qh.z * rhz + qh.w * rhw;
            }
            #pragma unroll
            for (int off = 1; off <= 8; off <<= 1) {
                p[0] += __shfl_xor_sync(FULLM, p[0], off);
                p[1] += __shfl_xor_sync(FULLM, p[1], off);
                p[2] += __shfl_xor_sync(FULLM, p[2], off);
                p[3] += __shfl_xor_sync(FULLM, p[3], off);
            }
            m0 = fmaxf(m0, p[0]); m1 = fmaxf(m1, p[1]);
            m2 = fmaxf(m2, p[2]); m3 = fmaxf(m3, p[3]);
            if (c == 0) sm.sc_sm[w * CSM + s] = make_float4(p[0], p[1], p[2], p[3]);
        }
        __syncthreads();
    }

    // merge the two half-warp maxima
    m0 = fmaxf(m0, __shfl_xor_sync(FULLM, m0, 16));
    m1 = fmaxf(m1, __shfl_xor_sync(FULLM, m1, 16));
    m2 = fmaxf(m2, __shfl_xor_sync(FULLM, m2, 16));
    m3 = fmaxf(m3, __shfl_xor_sync(FULLM, m3, 16));

    // lead-in prefetch of the first 8 V rows
    if (l < 4) {
        #pragma unroll
        for (int s = 0; s < 8; s++) {
            int slot = sm.slot_sm[s];
            if (slot >= 0)
                l2_prefetch(vc + (size_t)slot * ROWF + w * DD + l * 32);
        }
    }

    // ---- scores -> exp weights in shared; accumulate l-sums (constant bounds) ----
    float l0 = 0.f, l1 = 0.f, l2 = 0.f, l3 = 0.f;
    #pragma unroll
    for (int s0i = 0; s0i < NR; s0i += 32) {
        int s = s0i + l;
        if (s < NR) {
            float4 sc = sm.sc_sm[w * CSM + s];
            sc.x = __expf(sc.x - m0); sc.y = __expf(sc.y - m1);
            sc.z = __expf(sc.z - m2); sc.w = __expf(sc.w - m3);
            sm.sc_sm[w * CSM + s] = sc;
            l0 += sc.x; l1 += sc.y; l2 += sc.z; l3 += sc.w;
        }
    }
    #pragma unroll
    for (int off = 16; off > 0; off >>= 1) {
        l0 += __shfl_xor_sync(FULLM, l0, off);
        l1 += __shfl_xor_sync(FULLM, l1, off);
        l2 += __shfl_xor_sync(FULLM, l2, off);
        l3 += __shfl_xor_sync(FULLM, l3, off);
    }
    __syncwarp();

    // ---- V phase: lane owns dims 4l..4l+3, one row per iteration ----
    float4 a0 = make_float4(0,0,0,0), a1 = a0, a2 = a0, a3 = a0;
    #pragma unroll 4
    for (int s = 0; s < NR; s++) {
        {
            int sf = s + 4;
            if (sf < NR) {
                int slotf = sm.slot_sm[sf];
                if (slotf >= 0)
                    l2_prefetch(vc + (size_t)slotf * ROWF + w * DD + 4 * l);
            }
        }
        const float4 e = sm.sc_sm[w * CSM + s];
        const int slot = sm.slot_sm[s];
        float4 v4 = make_float4(0.f, 0.f, 0.f, 0.f);
        if (slot >= 0)
            v4 = *(const float4*)(vc + (size_t)slot * ROWF + w * DD + 4 * l);
        a0.x += e.x * v4.x; a0.y += e.x * v4.y; a0.z += e.x * v4.z; a0.w += e.x * v4.w;
        a1.x += e.y * v4.x; a1.y += e.y * v4.y; a1.z += e.y * v4.z; a1.w += e.y * v4.w;
        a2.x += e.z * v4.x; a2.y += e.z * v4.y; a2.z += e.z * v4.z; a2.w += e.z * v4.w;
        a3.x += e.w * v4.x; a3.y += e.w * v4.y; a3.z += e.w * v4.z; a3.w += e.w * v4.w;
    }

    // ---- Write partials (float4, coalesced) ----
    {
        size_t base = (((size_t)b * NCHUNK + chunk) * HH + w * 4) * DD;
        float4* ga = (float4*)g_acc;
        ga[(base >> 2) + l]            = a0;
        ga[((base + DD) >> 2) + l]     = a1;
        ga[((base + 2 * DD) >> 2) + l] = a2;
        ga[((base + 3 * DD) >> 2) + l] = a3;
    }
    if (l == 0) {
        int mb = (b * NCHUNK + chunk) * HH + w * 4;
        g_m[mb + 0] = m0; g_m[mb + 1] = m1; g_m[mb + 2] = m2; g_m[mb + 3] = m3;
        g_l[mb + 0] = l0; g_l[mb + 1] = l1; g_l[mb + 2] = l2; g_l[mb + 3] = l3;
    }
}

__global__ __launch_bounds__(NT, 4) void attn_partial(
    const float* __restrict__ q,
    const float* __restrict__ kc,
    const float* __restrict__ vc,
    const int*   __restrict__ slot_map,
    const int*   __restrict__ pos)
{
    __shared__ SmemT sm;

    const int b     = blockIdx.y;
    const int chunk = blockIdx.x;
    const int s0    = chunk * CSM;
    const int nrows = (SS - s0 < CSM) ? (SS - s0) : CSM;   // 56 (chunks 0-35) or 32 (chunk 36)
    const int tid   = threadIdx.x;

    if (tid < 64) {
        float fi = (float)tid * 0.015625f;
        sm.invf_sm[tid] = expf(-fi * 9.210340371976184f);
    }
    if (tid < CSM) {
        if (tid < nrows) {
            sm.slot_sm[tid] = slot_map[b * SS + s0 + tid];
            sm.pos_sm[tid]  = (float)pos[b * SS + s0 + tid];
        } else {
            sm.slot_sm[tid] = -1;
            sm.pos_sm[tid]  = 0.f;
        }
    }
    __syncthreads();

    if (chunk < NCHUNK - 1)
        partial_body<CSM>(sm, q, kc, vc, b, chunk);
    else
        partial_body<32>(sm, q, kc, vc, b, chunk);
}

// Combine: one block per (b,h); 4 warps x 9 chunks (constant) + warp0 takes chunk 36.
#define CPW 9
__global__ __launch_bounds__(128) void attn_combine(float* __restrict__ out)
{
    __shared__ float4 osm[4][32];
    __shared__ float  Lsm[4];

    const int bh = blockIdx.x;
    const int b  = bh >> 5;
    const int h  = bh & 31;
    const int wj = threadIdx.x >> 5;
    const int l  = threadIdx.x & 31;

    // global max over 37 chunks
    float ma  = g_m[(b * NCHUNK + l) * HH + h];
    float mb2 = (l < NCHUNK - 32) ? g_m[(b * NCHUNK + 32 + l) * HH + h] : -1e30f;
    float M = fmaxf(ma, mb2);
    #pragma unroll
    for (int off = 16; off > 0; off >>= 1)
        M = fmaxf(M, __shfl_xor_sync(FULLM, M, off));

    float al[CPW];
    #pragma unroll
    for (int k = 0; k < CPW; k++)
        al[k] = __expf(g_m[(b * NCHUNK + wj * CPW + k) * HH + h] - M);

    float L = 0.f;
    float4 o = make_float4(0.f, 0.f, 0.f, 0.f);
    #pragma unroll
    for (int k = 0; k < CPW; k++) {
        int idx = (b * NCHUNK + wj * CPW + k) * HH + h;
        L += al[k] * g_l[idx];
        float4 a = ((const float4*)g_acc)[(((size_t)idx * DD) >> 2) + l];
        o.x += al[k] * a.x; o.y += al[k] * a.y;
        o.z += al[k] * a.z; o.w += al[k] * a.w;
    }
    // chunk 36 on warp 0
    if (wj == 0) {
        int idx = (b * NCHUNK + 36) * HH + h;
        float a36 = __expf(g_m[idx] - M);
        L += a36 * g_l[idx];
        float4 a = ((const float4*)g_acc)[(((size_t)idx * DD) >> 2) + l];
        o.x += a36 * a.x; o.y += a36 * a.y;
        o.z += a36 * a.z; o.w += a36 * a.w;
    }
    osm[wj][l] = o;
    if (l == 0) Lsm[wj] = L;
    __syncthreads();

    if (wj == 0) {
        float4 t1 = osm[1][l], t2 = osm[2][l], t3 = osm[3][l];
        o.x += t1.x + t2.x + t3.x;
        o.y += t1.y + t2.y + t3.y;
        o.z += t1.z + t2.z + t3.z;
        o.w += t1.w + t2.w + t3.w;
        float inv = 1.0f / (Lsm[0] + Lsm[1] + Lsm[2] + Lsm[3]);
        o.x *= inv; o.y *= inv; o.z *= inv; o.w *= inv;
        ((float4*)out)[(size_t)bh * 32 + l] = o;
    }
}

extern "C" void kernel_launch(void* const* d_in, const int* in_sizes, int n_in,
                              void* d_out, int out_size) {
    const float* query   = (const float*)d_in[0];
    const float* k_cache = (const float*)d_in[1];
    const float* v_cache = (const float*)d_in[2];
    const int*   slots   = (const int*)d_in[3];
    const int*   pos     = (const int*)d_in[4];
    float*       out     = (float*)d_out;

    attn_partial<<<dim3(NCHUNK, BB), NT>>>(query, k_cache, v_cache, slots, pos);
    attn_combine<<<BB * HH, 128>>>(out);
}

// round 11
// speedup vs baseline: 1.5396x; 1.0665x over previous
#include <cuda_runtime.h>
#include <math.h>

#define BB      32
#define HH      32
#define KVHN    8
#define DD      128
#define SS      2048
#define NCHUNK  32
#define CS      64            // positions per chunk
#define HCS     32            // positions per table pass
#define NT      256           // 8 warps = 8 kv heads
#define SCALE   0.08838834764831845f
#define ROWF    (KVHN*DD)     // floats per slot row (1024)
#define FULLM   0xffffffffu

__device__ float g_acc[(size_t)BB * NCHUNK * HH * DD];  // 16 MB
__device__ float g_m[BB * NCHUNK * HH];
__device__ float g_l[BB * NCHUNK * HH];

__device__ __forceinline__ void l2_prefetch(const void* p) {
    asm volatile("prefetch.global.L2 [%0];" :: "l"(p));
}

// fp32 Cody-Waite reduction into [-pi,pi], then MUFU fast sin/cos.
__device__ __forceinline__ void rope_sincos(float ang, float* s, float* c) {
    const float INV2PI = 0.15915494309189535f;
    const float C1 = 6.28125f;
    const float C2 = 0.0019353071795864769f;
    float n = rintf(ang * INV2PI);
    float r = fmaf(-n, C1, ang);
    r = fmaf(-n, C2, r);
    *s = __sinf(r);
    *c = __cosf(r);
}

__global__ __launch_bounds__(NT, 4) void attn_partial(
    const float* __restrict__ q,
    const float* __restrict__ kc,
    const float* __restrict__ vc,
    const int*   __restrict__ slot_map,
    const int*   __restrict__ pos)
{
    __shared__ float  cos_tab[HCS * 64];          // 8 KB (per pass)
    __shared__ float  sin_tab[HCS * 64];          // 8 KB
    __shared__ float4 q_sm[KVHN * 4 * 2 * 16];    // 16 KB  [head j][lo/hi][c]
    __shared__ float4 sc_sm[KVHN * CS];           // 8 KB   scores -> exp weights
    __shared__ int    slot_sm[CS];
    __shared__ float  pos_sm[CS];
    __shared__ float  invf_sm[64];

    const int b     = blockIdx.y;
    const int chunk = blockIdx.x;
    const int s0    = chunk * CS;
    const int tid   = threadIdx.x;
    const int w     = tid >> 5;            // warp = kv head
    const int l     = tid & 31;
    const int c     = l & 15;              // float4 chunk within row (K phase)
    const int r     = l >> 4;              // row parity within pair

    if (tid < 64) {
        float fi = (float)tid * 0.015625f;
        invf_sm[tid] = expf(-fi * 9.210340371976184f);
    }
    if (tid < CS) {
        slot_sm[tid] = slot_map[b * SS + s0 + tid];
        pos_sm[tid]  = (float)pos[b * SS + s0 + tid];
    }
    __syncthreads();

    // Warm L2 for the first 32 K rows while the prologue runs.
    {
        int sw = tid >> 3;
        int lc = tid & 7;
        int slot = slot_sm[sw];
        if (slot >= 0)
            l2_prefetch(kc + (size_t)slot * ROWF + (w & 3) * 2 * DD + lc * 32);
    }

    // Rope q (4 heads per warp) for dims {4c..4c+3, +64}; fold SCALE; store to shared.
    if (r == 0) {
        float pq = (float)pos[b * SS + SS - 1];
        float cq[4], sq[4];
        #pragma unroll
        for (int i = 0; i < 4; i++)
            rope_sincos(pq * invf_sm[4 * c + i], &sq[i], &cq[i]);
        #pragma unroll
        for (int j = 0; j < 4; j++) {
            const float4* qp = (const float4*)(q + ((size_t)(b * HH + w * 4 + j)) * DD);
            float4 alo = qp[c];
            float4 ahi = qp[c + 16];
            float4 ql, qh;
            ql.x = SCALE * (alo.x * cq[0] - ahi.x * sq[0]);
            qh.x = SCALE * (ahi.x * cq[0] + alo.x * sq[0]);
            ql.y = SCALE * (alo.y * cq[1] - ahi.y * sq[1]);
            qh.y = SCALE * (ahi.y * cq[1] + alo.y * sq[1]);
            ql.z = SCALE * (alo.z * cq[2] - ahi.z * sq[2]);
            qh.z = SCALE * (ahi.z * cq[2] + alo.z * sq[2]);
            ql.w = SCALE * (alo.w * cq[3] - ahi.w * sq[3]);
            qh.w = SCALE * (ahi.w * cq[3] + alo.w * sq[3]);
            q_sm[((w * 4 + j) * 2 + 0) * 16 + c] = ql;
            q_sm[((w * 4 + j) * 2 + 1) * 16 + c] = qh;
        }
    }

    // ---- K phase in two passes of HCS positions; SW-pipelined loads ----
    float m0 = -1e30f, m1 = -1e30f, m2 = -1e30f, m3 = -1e30f;

    #pragma unroll
    for (int pass = 0; pass < 2; pass++) {
        // Prologue load of this pass's first row pair (independent of table).
        float4 klo = make_float4(0.f, 0.f, 0.f, 0.f);
        float4 khi = make_float4(0.f, 0.f, 0.f, 0.f);
        {
            const int sfirst = pass * HCS + r;
            const int slot = slot_sm[sfirst];
            if (slot >= 0) {
                const float* kp = kc + (size_t)slot * ROWF + w * DD + 4 * c;
                klo = *(const float4*)kp;
                khi = *(const float4*)(kp + 64);
            }
        }

        // Build cos/sin for positions [pass*HCS, pass*HCS+HCS) — overlaps the load.
        for (int idx = tid; idx < HCS * 64; idx += NT) {
            int s = idx >> 6;
            int i = idx & 63;
            float sv, cv;
            rope_sincos(pos_sm[pass * HCS + s] * invf_sm[i], &sv, &cv);
            cos_tab[idx] = cv;
            sin_tab[idx] = sv;
        }
        __syncthreads();

        #pragma unroll 4
        for (int sp = 0; sp < HCS; sp += 2) {
            const int sl = sp + r;                 // table-local position
            const int s  = pass * HCS + sl;        // chunk-local position

            // prefetch K row 12 positions ahead into L2
            {
                int sf = s + 12;
                if (sf < CS) {
                    int slotf = slot_sm[sf];
                    if (slotf >= 0) {
                        const float* pp = kc + (size_t)slotf * ROWF + w * DD + 4 * c;
                        l2_prefetch(pp);
                        l2_prefetch(pp + 64);
                    }
                }
            }

            // Preload NEXT iteration's row pair before touching this one's data.
            float4 nklo = make_float4(0.f, 0.f, 0.f, 0.f);
            float4 nkhi = make_float4(0.f, 0.f, 0.f, 0.f);
            if (sp + 2 < HCS) {
                const int nslot = slot_sm[s + 2];
                if (nslot >= 0) {
                    const float* np = kc + (size_t)nslot * ROWF + w * DD + 4 * c;
                    nklo = *(const float4*)np;
                    nkhi = *(const float4*)(np + 64);
                }
            }

            const float4 co = *(const float4*)&cos_tab[sl * 64 + 4 * c];
            const float4 si = *(const float4*)&sin_tab[sl * 64 + 4 * c];

            float rlx = klo.x * co.x - khi.x * si.x, rhx = khi.x * co.x + klo.x * si.x;
            float rly = klo.y * co.y - khi.y * si.y, rhy = khi.y * co.y + klo.y * si.y;
            float rlz = klo.z * co.z - khi.z * si.z, rhz = khi.z * co.z + klo.z * si.z;
            float rlw = klo.w * co.w - khi.w * si.w, rhw = khi.w * co.w + klo.w * si.w;

            float p[4];
            #pragma unroll
            for (int j = 0; j < 4; j++) {
                float4 ql = q_sm[((w * 4 + j) * 2 + 0) * 16 + c];
                float4 qh = q_sm[((w * 4 + j) * 2 + 1) * 16 + c];
                p[j] = ql.x * rlx + ql.y * rly + ql.z * rlz + ql.w * rlw
                     + qh.x * rhx + qh.y * rhy + qh.z * rhz + qh.w * rhw;
            }
            #pragma unroll
            for (int off = 1; off <= 8; off <<= 1) {
                p[0] += __shfl_xor_sync(FULLM, p[0], off);
                p[1] += __shfl_xor_sync(FULLM, p[1], off);
                p[2] += __shfl_xor_sync(FULLM, p[2], off);
                p[3] += __shfl_xor_sync(FULLM, p[3], off);
            }
            m0 = fmaxf(m0, p[0]); m1 = fmaxf(m1, p[1]);
            m2 = fmaxf(m2, p[2]); m3 = fmaxf(m3, p[3]);
            if (c == 0) sc_sm[w * CS + s] = make_float4(p[0], p[1], p[2], p[3]);

            klo = nklo; khi = nkhi;
        }
        __syncthreads();   // protect table before rebuild / reuse
    }

    // merge the two half-warp maxima
    m0 = fmaxf(m0, __shfl_xor_sync(FULLM, m0, 16));
    m1 = fmaxf(m1, __shfl_xor_sync(FULLM, m1, 16));
    m2 = fmaxf(m2, __shfl_xor_sync(FULLM, m2, 16));
    m3 = fmaxf(m3, __shfl_xor_sync(FULLM, m3, 16));

    // lead-in prefetch of the first 8 V rows
    if (l < 4) {
        #pragma unroll
        for (int s = 0; s < 8; s++) {
            int slot = slot_sm[s];
            if (slot >= 0)
                l2_prefetch(vc + (size_t)slot * ROWF + w * DD + l * 32);
        }
    }

    // ---- scores -> exp weights in shared (4 MUFU per lane total) ----
    {
        float4 sca = sc_sm[w * CS + l];
        sca.x = __expf(sca.x - m0); sca.y = __expf(sca.y - m1);
        sca.z = __expf(sca.z - m2); sca.w = __expf(sca.w - m3);
        sc_sm[w * CS + l] = sca;
        float4 scb = sc_sm[w * CS + 32 + l];
        scb.x = __expf(scb.x - m0); scb.y = __expf(scb.y - m1);
        scb.z = __expf(scb.z - m2); scb.w = __expf(scb.w - m3);
        sc_sm[w * CS + 32 + l] = scb;
    }
    __syncwarp();

    // ---- V phase: lane owns dims 4l..4l+3; SW-pipelined loads ----
    float4 a0 = make_float4(0,0,0,0), a1 = a0, a2 = a0, a3 = a0;
    float l0 = 0.f, l1 = 0.f, l2 = 0.f, l3 = 0.f;

    float4 v4 = make_float4(0.f, 0.f, 0.f, 0.f);
    {
        int slot = slot_sm[0];
        if (slot >= 0)
            v4 = *(const float4*)(vc + (size_t)slot * ROWF + w * DD + 4 * l);
    }

    #pragma unroll 4
    for (int s = 0; s < CS; s++) {
        // prefetch V row 8 ahead
        {
            int sf = s + 8;
            if (sf < CS) {
                int slotf = slot_sm[sf];
                if (slotf >= 0)
                    l2_prefetch(vc + (size_t)slotf * ROWF + w * DD + 4 * l);
            }
        }
        // preload next row before consuming current
        float4 nv4 = make_float4(0.f, 0.f, 0.f, 0.f);
        if (s + 1 < CS) {
            int nslot = slot_sm[s + 1];
            if (nslot >= 0)
                nv4 = *(const float4*)(vc + (size_t)nslot * ROWF + w * DD + 4 * l);
        }

        const float4 e = sc_sm[w * CS + s];     // broadcast
        l0 += e.x; l1 += e.y; l2 += e.z; l3 += e.w;
        a0.x += e.x * v4.x; a0.y += e.x * v4.y; a0.z += e.x * v4.z; a0.w += e.x * v4.w;
        a1.x += e.y * v4.x; a1.y += e.y * v4.y; a1.z += e.y * v4.z; a1.w += e.y * v4.w;
        a2.x += e.z * v4.x; a2.y += e.z * v4.y; a2.z += e.z * v4.z; a2.w += e.z * v4.w;
        a3.x += e.w * v4.x; a3.y += e.w * v4.y; a3.z += e.w * v4.z; a3.w += e.w * v4.w;

        v4 = nv4;
    }

    // ---- Write partials (float4, coalesced) ----
    {
        size_t base = (((size_t)b * NCHUNK + chunk) * HH + w * 4) * DD;
        float4* ga = (float4*)g_acc;
        ga[(base >> 2) + l]            = a0;
        ga[((base + DD) >> 2) + l]     = a1;
        ga[((base + 2 * DD) >> 2) + l] = a2;
        ga[((base + 3 * DD) >> 2) + l] = a3;
    }
    if (l == 0) {
        int mb = (b * NCHUNK + chunk) * HH + w * 4;
        g_m[mb + 0] = m0; g_m[mb + 1] = m1; g_m[mb + 2] = m2; g_m[mb + 3] = m3;
        g_l[mb + 0] = l0; g_l[mb + 1] = l1; g_l[mb + 2] = l2; g_l[mb + 3] = l3;
    }
}

// Combine: one block per (b,h); 4 warps x 8 chunks each; merge via shared.
__global__ __launch_bounds__(128) void attn_combine(float* __restrict__ out)
{
    __shared__ float4 osm[4][32];
    __shared__ float  Lsm[4];

    const int bh = blockIdx.x;
    const int b  = bh >> 5;
    const int h  = bh & 31;
    const int wj = threadIdx.x >> 5;
    const int l  = threadIdx.x & 31;

    float mraw = g_m[(b * NCHUNK + l) * HH + h];
    float M = mraw;
    #pragma unroll
    for (int off = 16; off > 0; off >>= 1)
        M = fmaxf(M, __shfl_xor_sync(FULLM, M, off));

    // precompute all 8 alpha factors so the load loop has full MLP
    float al[8];
    #pragma unroll
    for (int k = 0; k < 8; k++)
        al[k] = __expf(__shfl_sync(FULLM, mraw, wj * 8 + k) - M);

    float L = 0.f;
    float4 o = make_float4(0.f, 0.f, 0.f, 0.f);
    #pragma unroll
    for (int k = 0; k < 8; k++) {
        int idx = (b * NCHUNK + wj * 8 + k) * HH + h;
        L += al[k] * g_l[idx];
        float4 a = ((const float4*)g_acc)[(((size_t)idx * DD) >> 2) + l];
        o.x += al[k] * a.x; o.y += al[k] * a.y;
        o.z += al[k] * a.z; o.w += al[k] * a.w;
    }
    osm[wj][l] = o;
    if (l == 0) Lsm[wj] = L;
    __syncthreads();

    if (wj == 0) {
        float4 t1 = osm[1][l], t2 = osm[2][l], t3 = osm[3][l];
        o.x += t1.x + t2.x + t3.x;
        o.y += t1.y + t2.y + t3.y;
        o.z += t1.z + t2.z + t3.z;
        o.w += t1.w + t2.w + t3.w;
        float inv = 1.0f / (Lsm[0] + Lsm[1] + Lsm[2] + Lsm[3]);
        o.x *= inv; o.y *= inv; o.z *= inv; o.w *= inv;
        ((float4*)out)[(size_t)bh * 32 + l] = o;
    }
}

extern "C" void kernel_launch(void* const* d_in, const int* in_sizes, int n_in,
                              void* d_out, int out_size) {
    const float* query   = (const float*)d_in[0];
    const float* k_cache = (const float*)d_in[1];
    const float* v_cache = (const float*)d_in[2];
    const int*   slots   = (const int*)d_in[3];
    const int*   pos     = (const int*)d_in[4];
    float*       out     = (float*)d_out;

    attn_partial<<<dim3(NCHUNK, BB), NT>>>(query, k_cache, v_cache, slots, pos);
    attn_combine<<<BB * HH, 128>>>(out);
}